// round 16
// baseline (speedup 1.0000x reference)
#include <cuda_runtime.h>
#include <cuda_bf16.h>
#include <cuda_fp16.h>
#include <math.h>
#include <stdint.h>

// Problem constants
#define BB 2
#define TT 2048
#define DD 1024
#define HH 16
#define DHH 64
#define FF 4096
#define MM (BB*TT)          // 4096 rows
#define QLD (3*DD)          // merged qkv row stride

// ---------------------------------------------------------------------------
// Baseline-PTX tensor helpers (sm_80-era: mma.sync / ldmatrix / cp.async)
// ---------------------------------------------------------------------------
__device__ __forceinline__ uint32_t smem_u32(const void* p) {
    uint32_t a;
    asm("{ .reg .u64 t; cvta.to.shared.u64 t, %1; cvt.u32.u64 %0, t; }" : "=r"(a) : "l"(p));
    return a;
}
__device__ __forceinline__ void cpa16(uint32_t dst, const void* src) {
    asm volatile("cp.async.cg.shared.global [%0], [%1], 16;" :: "r"(dst), "l"(src) : "memory");
}
#define CP_COMMIT() asm volatile("cp.async.commit_group;" ::: "memory")
#define CP_WAIT0()  asm volatile("cp.async.wait_group 0;" ::: "memory")
#define CP_WAIT1()  asm volatile("cp.async.wait_group 1;" ::: "memory")

#define LDM4(r, a) \
    asm volatile("ldmatrix.sync.aligned.m8n8.x4.shared.b16 {%0,%1,%2,%3}, [%4];" \
        : "=r"((r)[0]), "=r"((r)[1]), "=r"((r)[2]), "=r"((r)[3]) : "r"(a))
#define LDM4T(r, a) \
    asm volatile("ldmatrix.sync.aligned.m8n8.x4.trans.shared.b16 {%0,%1,%2,%3}, [%4];" \
        : "=r"((r)[0]), "=r"((r)[1]), "=r"((r)[2]), "=r"((r)[3]) : "r"(a))

__device__ __forceinline__ void mma_bf16(float* d, const uint32_t* a, const uint32_t* b) {
    asm volatile("mma.sync.aligned.m16n8k16.row.col.f32.bf16.bf16.f32 "
        "{%0,%1,%2,%3}, {%4,%5,%6,%7}, {%8,%9}, {%0,%1,%2,%3};"
        : "+f"(d[0]), "+f"(d[1]), "+f"(d[2]), "+f"(d[3])
        : "r"(a[0]), "r"(a[1]), "r"(a[2]), "r"(a[3]), "r"(b[0]), "r"(b[1]));
}
__device__ __forceinline__ void mma_fp16(float* d, const uint32_t* a, const uint32_t* b) {
    asm volatile("mma.sync.aligned.m16n8k16.row.col.f32.f16.f16.f32 "
        "{%0,%1,%2,%3}, {%4,%5,%6,%7}, {%8,%9}, {%0,%1,%2,%3};"
        : "+f"(d[0]), "+f"(d[1]), "+f"(d[2]), "+f"(d[3])
        : "r"(a[0]), "r"(a[1]), "r"(a[2]), "r"(a[3]), "r"(b[0]), "r"(b[1]));
}

__device__ __forceinline__ uint32_t pkbf(float lo, float hi) {
    uint32_t d;
    asm("cvt.rn.bf16x2.f32 %0, %1, %2;" : "=r"(d) : "f"(hi), "f"(lo));
    return d;
}
__device__ __forceinline__ uint32_t pkhf(float lo, float hi) {
    uint32_t d;
    asm("cvt.rn.f16x2.f32 %0, %1, %2;" : "=r"(d) : "f"(hi), "f"(lo));
    return d;
}

// ---------------------------------------------------------------------------
// Scratch (allocation-free: __device__ globals)
// ---------------------------------------------------------------------------
__device__ float g_y[MM*DD];
__device__ float g_x[MM*DD];
__device__ unsigned char g_mask[TT*TT];
__device__ int g_mask_mode;

__device__ __nv_bfloat16 g_srcB[MM*DD];
__device__ __nv_bfloat16 g_qkvB[MM*QLD];          // merged q|k|v output
__device__ __nv_bfloat16 g_attnB[MM*DD];
__device__ __half        g_xF[MM*DD];
__device__ __half        g_hF[MM*FF];
__device__ __nv_bfloat16 g_qkvw[QLD*DD];          // q_w | k_w | v_w rows
__device__ float         g_qkvb[QLD];
__device__ __nv_bfloat16 g_owH[DD*DD];
__device__ __half        g_l1F[FF*DD];
__device__ __half        g_l2F[DD*FF];

// ---------------------------------------------------------------------------
// One fused conversion kernel: all weights + src. float4 per thread.
// Layout (float4 index):
//   [0, 3*WQ)          : q_w|k_w|v_w -> g_qkvw (bf16)
//   [3WQ, 4WQ)         : o_w -> g_owH (bf16)
//   [4WQ, 4WQ+L1)      : l1_w -> g_l1F (fp16)
//   [.., +L1)          : l2_w -> g_l2F (fp16)
//   [.., +L1)          : src -> g_srcB (bf16)
// WQ = DD*DD/4 = 262144, L1 = FF*DD/4 = 1048576; total = 4194304 -> 16384 blocks
// ---------------------------------------------------------------------------
__global__ __launch_bounds__(256)
void convert_all(const float* __restrict__ qw, const float* __restrict__ kw,
                 const float* __restrict__ vw, const float* __restrict__ ow,
                 const float* __restrict__ l1w, const float* __restrict__ l2w,
                 const float* __restrict__ src)
{
    const int WQ = DD*DD/4;
    const int L1 = FF*DD/4;
    int i = blockIdx.x * 256 + threadIdx.x;
    if (i < 4*WQ) {
        int t = i / WQ;
        int j = i - t*WQ;
        const float* w = (t == 0) ? qw : (t == 1) ? kw : (t == 2) ? vw : ow;
        float4 v = ((const float4*)w)[j];
        uint2 o = make_uint2(pkbf(v.x, v.y), pkbf(v.z, v.w));
        if (t < 3) ((uint2*)g_qkvw)[i] = o;
        else       ((uint2*)g_owH)[j] = o;
    } else {
        int r = i - 4*WQ;
        int t = r / L1;
        int j = r - t*L1;
        const float* w = (t == 0) ? l1w : (t == 1) ? l2w : src;
        float4 v = ((const float4*)w)[j];
        if (t == 0)      ((uint2*)g_l1F)[j] = make_uint2(pkhf(v.x, v.y), pkhf(v.z, v.w));
        else if (t == 1) ((uint2*)g_l2F)[j] = make_uint2(pkhf(v.x, v.y), pkhf(v.z, v.w));
        else             ((uint2*)g_srcB)[j] = make_uint2(pkbf(v.x, v.y), pkbf(v.z, v.w));
    }
}

__global__ __launch_bounds__(256)
void concat_bias(const float* __restrict__ qb, const float* __restrict__ kb,
                 const float* __restrict__ vb)
{
    int i = blockIdx.x * 256 + threadIdx.x;
    if (i >= QLD) return;
    g_qkvb[i] = (i < DD) ? qb[i] : (i < 2*DD) ? kb[i - DD] : vb[i - 2*DD];
}

// ---------------------------------------------------------------------------
// Mask dtype detection (prefix scan) + convert
// ---------------------------------------------------------------------------
__global__ __launch_bounds__(1024)
void mask_scan_kernel(const uint32_t* __restrict__ m)
{
    const int tid = threadIdx.x;
    int u8f = 0, f32f = 0;
    const int NW = 65536;
    for (int i = tid; i < NW; i += 1024) {
        uint32_t w = m[i];
        if (w != 0u && w != 1u && w != 0x3F800000u) u8f = 1;
        if (w == 0x3F800000u) f32f = 1;
    }
    __shared__ int s_u8, s_f32;
    if (tid == 0) { s_u8 = 0; s_f32 = 0; }
    __syncthreads();
    if (u8f)  atomicOr(&s_u8, 1);
    if (f32f) atomicOr(&s_f32, 1);
    __syncthreads();
    if (tid == 0)
        g_mask_mode = s_u8 ? 0 : (s_f32 ? 2 : 1);
}

__global__ __launch_bounds__(256)
void mask_convert_kernel(const void* __restrict__ min)
{
    const int mode = g_mask_mode;
    int i = blockIdx.x * blockDim.x + threadIdx.x;
    const int NW = (TT*TT) / 4;
    if (i >= NW) return;
    uint32_t out;
    if (mode == 0) {
        out = ((const uint32_t*)min)[i];
    } else if (mode == 1) {
        const int* p = (const int*)min;
        out  = (uint32_t)(p[4*i+0] != 0);
        out |= (uint32_t)(p[4*i+1] != 0) << 8;
        out |= (uint32_t)(p[4*i+2] != 0) << 16;
        out |= (uint32_t)(p[4*i+3] != 0) << 24;
    } else {
        const float* p = (const float*)min;
        out  = (uint32_t)(p[4*i+0] != 0.f);
        out |= (uint32_t)(p[4*i+1] != 0.f) << 8;
        out |= (uint32_t)(p[4*i+2] != 0.f) << 16;
        out |= (uint32_t)(p[4*i+3] != 0.f) << 24;
    }
    ((uint32_t*)g_mask)[i] = out;
}

// ---------------------------------------------------------------------------
// 1-term GEMM via mma.sync, 3-stage cp.async pipeline.
// acc = A[m,k] * B[n,k]
// EPI: 2 = res + alpha*(acc+bias) -> f32 C
//      3 = bias -> 16-bit out
//      5 = bias+relu -> 16-bit out
// HALF: 0 = bf16, 1 = fp16
// ---------------------------------------------------------------------------
#define TILE_B   16384                 // 128 rows x 128 bytes (64 halves)
#define BSTAGE_B (2*TILE_B)
#define GBF_DYN  (3*BSTAGE_B + 1024)   // 3 stages

#define STAGE_CHUNK(st, k0) do { \
    _Pragma("unroll") \
    for (int j = 0; j < 4; j++) { \
        const int c = sc0 + j; \
        const uint32_t sw = swrowbase + ((uint32_t)(c ^ rx) << 4); \
        cpa16((st) + sw,          A + (size_t)(bm + srow) * K + (k0) + c * 8); \
        cpa16((st) + TILE_B + sw, B + (size_t)(bn + srow) * K + (k0) + c * 8); \
    } } while (0)

template<int EPI, int HALF>
__global__ __launch_bounds__(256, 2)
void gemm_bf(const void* __restrict__ Av, const void* __restrict__ Bv,
             const float* __restrict__ bias, float* __restrict__ C,
             int M, int N, int K,
             const float* __restrict__ res, const float* __restrict__ alpha_p,
             void* __restrict__ outv)
{
    const uint16_t* A = (const uint16_t*)Av;
    const uint16_t* B = (const uint16_t*)Bv;
    uint16_t* out = (uint16_t*)outv;

    extern __shared__ unsigned char sm[];
    const uint32_t smu  = smem_u32(sm);
    const uint32_t base = (smu + 1023) & ~1023u;

    const int tid  = threadIdx.x;
    const int wid  = tid >> 5;
    const int lane = tid & 31;
    const int wm   = wid >> 2;
    const int wn   = wid & 3;
    const int bm   = blockIdx.y * 128;
    const int bn   = blockIdx.x * 128;

    float d[4][4][4];
    #pragma unroll
    for (int i = 0; i < 4; i++)
        #pragma unroll
        for (int j = 0; j < 4; j++)
            #pragma unroll
            for (int q = 0; q < 4; q++) d[i][j][q] = 0.f;

    const int srow = tid >> 1;
    const int sc0  = (tid & 1) * 4;
    const uint32_t swrowbase = (uint32_t)srow * 128;
    const int rx = srow & 7;

    const int NC = K >> 6;

    // Prologue: chunks 0 and 1
    STAGE_CHUNK(base, 0);
    CP_COMMIT();
    if (NC > 1) STAGE_CHUNK(base + BSTAGE_B, 64);
    CP_COMMIT();

    for (int ch = 0; ch < NC; ch++) {
        CP_WAIT1();            // group for chunk ch complete
        __syncthreads();       // everyone done computing ch-1, data for ch visible

        if (ch + 2 < NC) {
            const uint32_t st = base + ((ch + 2) % 3) * BSTAGE_B;
            STAGE_CHUNK(st, (size_t)(ch + 2) * 64);
        }
        CP_COMMIT();           // keep group count consistent (may be empty)

        const uint32_t st = base + (ch % 3) * BSTAGE_B;
        const uint32_t aS = st, bS = st + TILE_B;

        const int arow_base = wm * 64 + (lane & 15);
        const int akh = lane >> 4;
        const int brow_base = wn * 32 + (lane & 7) + ((lane >> 4) << 3);
        const int bkh = (lane >> 3) & 1;

        #pragma unroll
        for (int k16 = 0; k16 < 4; k16++) {
            uint32_t a[4][4], b[2][4];
            #pragma unroll
            for (int mt = 0; mt < 4; mt++) {
                const int row = arow_base + mt * 16;
                const uint32_t cb = (uint32_t)(k16 * 32 + akh * 16);
                LDM4(a[mt], aS + (uint32_t)row * 128 + (cb ^ ((uint32_t)(row & 7) << 4)));
            }
            #pragma unroll
            for (int bt = 0; bt < 2; bt++) {
                const int row = brow_base + bt * 16;
                const uint32_t cb = (uint32_t)(k16 * 32 + bkh * 16);
                LDM4(b[bt], bS + (uint32_t)row * 128 + (cb ^ ((uint32_t)(row & 7) << 4)));
            }
            #pragma unroll
            for (int mt = 0; mt < 4; mt++)
                #pragma unroll
                for (int nt = 0; nt < 4; nt++) {
                    if (HALF) mma_fp16(d[mt][nt], a[mt], &b[nt >> 1][(nt & 1) * 2]);
                    else      mma_bf16(d[mt][nt], a[mt], &b[nt >> 1][(nt & 1) * 2]);
                }
        }
    }

    float alpha = 0.f;
    if (EPI == 2) alpha = *alpha_p;
    const int g  = lane >> 2;
    const int nq = (lane & 3) * 2;

    #pragma unroll
    for (int mt = 0; mt < 4; mt++) {
        const int m0 = bm + wm * 64 + mt * 16 + g;
        #pragma unroll
        for (int nt = 0; nt < 4; nt++) {
            const int n = bn + wn * 32 + nt * 8 + nq;
            float2 b2 = *(const float2*)&bias[n];
            float2 o0 = make_float2(d[mt][nt][0] + b2.x, d[mt][nt][1] + b2.y);
            float2 o1 = make_float2(d[mt][nt][2] + b2.x, d[mt][nt][3] + b2.y);
            if (EPI == 5) {
                o0.x = fmaxf(o0.x, 0.f); o0.y = fmaxf(o0.y, 0.f);
                o1.x = fmaxf(o1.x, 0.f); o1.y = fmaxf(o1.y, 0.f);
            }
            if (EPI == 2) {
                float2 r0 = *(const float2*)&res[(size_t)m0 * N + n];
                float2 r1 = *(const float2*)&res[(size_t)(m0 + 8) * N + n];
                o0.x = r0.x + alpha * o0.x; o0.y = r0.y + alpha * o0.y;
                o1.x = r1.x + alpha * o1.x; o1.y = r1.y + alpha * o1.y;
                *(float2*)&C[(size_t)m0 * N + n]       = o0;
                *(float2*)&C[(size_t)(m0 + 8) * N + n] = o1;
            } else {
                uint32_t p0 = HALF ? pkhf(o0.x, o0.y) : pkbf(o0.x, o0.y);
                uint32_t p1 = HALF ? pkhf(o1.x, o1.y) : pkbf(o1.x, o1.y);
                *(uint32_t*)&out[(size_t)m0 * N + n]       = p0;
                *(uint32_t*)&out[(size_t)(m0 + 8) * N + n] = p1;
            }
        }
    }
}

// ---------------------------------------------------------------------------
// Tensor-core flash attention (bf16 mma, fp32 softmax, exp2 domain).
// Q/K/V read from merged qkv buffer (row stride QLD). bf16 output.
// ---------------------------------------------------------------------------
#define MPAD 80
#define KV_B  8192
#define MB_B  (128*MPAD)
#define BUF_B (2*KV_B + MB_B)
#define ATT_SMEM (16384 + 2*BUF_B + 1024)
#define SCL2 0.1803368801f   // 0.125 * log2(e)

__global__ __launch_bounds__(256, 2)
void flash_attn_tc(const __nv_bfloat16* __restrict__ QKV,
                   const unsigned char* __restrict__ mask,
                   __nv_bfloat16* __restrict__ OH)
{
    extern __shared__ unsigned char sm[];
    const uint32_t smu = smem_u32(sm);
    const uint32_t Qs  = (smu + 1023) & ~1023u;

    const int tid = threadIdx.x, wid = tid >> 5, lane = tid & 31;
    const int q0 = blockIdx.x * 128;
    const int h  = blockIdx.y, b = blockIdx.z;
    const size_t rowbase = (size_t)b * TT;
    const int colh = h * DHH;

    {
        const int r = tid >> 1, c0 = (tid & 1) * 4;
        const __nv_bfloat16* src = QKV + (rowbase + q0 + r) * QLD + colh;
        #pragma unroll
        for (int j = 0; j < 4; j++) {
            const int c = c0 + j;
            cpa16(Qs + r * 128 + ((uint32_t)(c ^ (r & 7)) << 4), src + c * 8);
        }
    }
    {
        const uint32_t Ks = Qs + 16384, Vs = Ks + KV_B, Ms = Vs + KV_B;
        const int r = tid >> 2;
        const int j2 = tid & 3;
        #pragma unroll
        for (int j = 0; j < 2; j++) {
            const int c = j2 * 2 + j;
            const uint32_t sw = r * 128 + ((uint32_t)(c ^ (r & 7)) << 4);
            cpa16(Ks + sw, QKV + (rowbase + r) * QLD + DD + colh + c * 8);
            cpa16(Vs + sw, QKV + (rowbase + r) * QLD + 2*DD + colh + c * 8);
        }
        const int mr = tid >> 1;
        #pragma unroll
        for (int j = 0; j < 2; j++) {
            const int c = (tid & 1) * 2 + j;
            cpa16(Ms + mr * MPAD + c * 16, mask + (size_t)(q0 + mr) * TT + c * 16);
        }
        CP_COMMIT();
    }

    float m0 = -1e30f, m1 = -1e30f, l0 = 0.f, l1 = 0.f;
    float o[8][4];
    #pragma unroll
    for (int i = 0; i < 8; i++)
        #pragma unroll
        for (int j = 0; j < 4; j++) o[i][j] = 0.f;

    uint32_t aQ[4][4];
    const int arow = wid * 16 + (lane & 15);
    const int akh  = lane >> 4;
    const int brow = (lane & 7) + ((lane >> 4) << 3);
    const int bkh  = (lane >> 3) & 1;
    const int r0   = lane >> 2;
    const int cq   = (lane & 3) * 2;

    const int NT = TT / 64;
    for (int st = 0; st < NT; st++) {
        if (st + 1 < NT) {
            const uint32_t base = Qs + 16384 + ((st + 1) & 1) * BUF_B;
            const uint32_t Ks = base, Vs = base + KV_B, Ms = base + 2*KV_B;
            const int s1 = (st + 1) * 64;
            const int r = tid >> 2, j2 = tid & 3;
            #pragma unroll
            for (int j = 0; j < 2; j++) {
                const int c = j2 * 2 + j;
                const uint32_t sw = r * 128 + ((uint32_t)(c ^ (r & 7)) << 4);
                cpa16(Ks + sw, QKV + (rowbase + s1 + r) * QLD + DD + colh + c * 8);
                cpa16(Vs + sw, QKV + (rowbase + s1 + r) * QLD + 2*DD + colh + c * 8);
            }
            const int mr = tid >> 1;
            #pragma unroll
            for (int j = 0; j < 2; j++) {
                const int c = (tid & 1) * 2 + j;
                cpa16(Ms + mr * MPAD + c * 16, mask + (size_t)(q0 + mr) * TT + s1 + c * 16);
            }
            CP_COMMIT();
            CP_WAIT1();
        } else {
            CP_WAIT0();
        }
        __syncthreads();

        if (st == 0) {
            #pragma unroll
            for (int kt = 0; kt < 4; kt++) {
                const uint32_t cb = (uint32_t)(kt * 32 + akh * 16);
                LDM4(aQ[kt], Qs + (uint32_t)arow * 128 + (cb ^ ((uint32_t)(arow & 7) << 4)));
            }
        }

        const uint32_t base = Qs + 16384 + (st & 1) * BUF_B;
        const uint32_t Ks = base, Vs = base + KV_B, Ms = base + 2*KV_B;

        float sacc[8][4];
        #pragma unroll
        for (int i = 0; i < 8; i++)
            #pragma unroll
            for (int j = 0; j < 4; j++) sacc[i][j] = 0.f;

        #pragma unroll
        for (int kt = 0; kt < 4; kt++) {
            uint32_t bK[4][4];
            #pragma unroll
            for (int bt = 0; bt < 4; bt++) {
                const int row = brow + bt * 16;
                const uint32_t cb = (uint32_t)(kt * 32 + bkh * 16);
                LDM4(bK[bt], Ks + (uint32_t)row * 128 + (cb ^ ((uint32_t)(row & 7) << 4)));
            }
            #pragma unroll
            for (int nt = 0; nt < 8; nt++)
                mma_bf16(sacc[nt], aQ[kt], &bK[nt >> 1][(nt & 1) * 2]);
        }

        // masked online softmax (log2 domain)
        const int mrow0 = wid * 16 + r0;
        float mx0 = -1e30f, mx1 = -1e30f;
        #pragma unroll
        for (int nt = 0; nt < 8; nt++) {
            uchar2 k0 = *(const uchar2*)(sm + (Ms - smu) + mrow0 * MPAD + nt * 8 + cq);
            uchar2 k1 = *(const uchar2*)(sm + (Ms - smu) + (mrow0 + 8) * MPAD + nt * 8 + cq);
            sacc[nt][0] = k0.x ? -1e30f : sacc[nt][0] * SCL2;
            sacc[nt][1] = k0.y ? -1e30f : sacc[nt][1] * SCL2;
            sacc[nt][2] = k1.x ? -1e30f : sacc[nt][2] * SCL2;
            sacc[nt][3] = k1.y ? -1e30f : sacc[nt][3] * SCL2;
            mx0 = fmaxf(mx0, fmaxf(sacc[nt][0], sacc[nt][1]));
            mx1 = fmaxf(mx1, fmaxf(sacc[nt][2], sacc[nt][3]));
        }
        mx0 = fmaxf(mx0, __shfl_xor_sync(0xffffffffu, mx0, 1));
        mx0 = fmaxf(mx0, __shfl_xor_sync(0xffffffffu, mx0, 2));
        mx1 = fmaxf(mx1, __shfl_xor_sync(0xffffffffu, mx1, 1));
        mx1 = fmaxf(mx1, __shfl_xor_sync(0xffffffffu, mx1, 2));

        const float mn0 = fmaxf(m0, mx0), mn1 = fmaxf(m1, mx1);
        const float af0 = exp2f(m0 - mn0), af1 = exp2f(m1 - mn1);
        float rs0 = 0.f, rs1 = 0.f;
        #pragma unroll
        for (int nt = 0; nt < 8; nt++) {
            float p0 = (sacc[nt][0] == -1e30f) ? 0.f : exp2f(sacc[nt][0] - mn0);
            float p1 = (sacc[nt][1] == -1e30f) ? 0.f : exp2f(sacc[nt][1] - mn0);
            float p2 = (sacc[nt][2] == -1e30f) ? 0.f : exp2f(sacc[nt][2] - mn1);
            float p3 = (sacc[nt][3] == -1e30f) ? 0.f : exp2f(sacc[nt][3] - mn1);
            sacc[nt][0] = p0; sacc[nt][1] = p1; sacc[nt][2] = p2; sacc[nt][3] = p3;
            rs0 += p0 + p1; rs1 += p2 + p3;
        }
        rs0 += __shfl_xor_sync(0xffffffffu, rs0, 1);
        rs0 += __shfl_xor_sync(0xffffffffu, rs0, 2);
        rs1 += __shfl_xor_sync(0xffffffffu, rs1, 1);
        rs1 += __shfl_xor_sync(0xffffffffu, rs1, 2);
        l0 = af0 * l0 + rs0;  m0 = mn0;
        l1 = af1 * l1 + rs1;  m1 = mn1;

        #pragma unroll
        for (int nt = 0; nt < 8; nt++) {
            o[nt][0] *= af0; o[nt][1] *= af0;
            o[nt][2] *= af1; o[nt][3] *= af1;
        }

        uint32_t pf[4][4];
        #pragma unroll
        for (int kt = 0; kt < 4; kt++) {
            pf[kt][0] = pkbf(sacc[2*kt][0],   sacc[2*kt][1]);
            pf[kt][1] = pkbf(sacc[2*kt][2],   sacc[2*kt][3]);
            pf[kt][2] = pkbf(sacc[2*kt+1][0], sacc[2*kt+1][1]);
            pf[kt][3] = pkbf(sacc[2*kt+1][2], sacc[2*kt+1][3]);
        }

        #pragma unroll
        for (int kt = 0; kt < 4; kt++) {
            #pragma unroll
            for (int nt2 = 0; nt2 < 4; nt2++) {
                uint32_t bV[4];
                const int rv = kt * 16 + (lane & 15);
                const uint32_t c = (uint32_t)(nt2 * 2 + (lane >> 4));
                LDM4T(bV, Vs + (uint32_t)rv * 128 + ((c ^ (uint32_t)(rv & 7)) << 4));
                mma_bf16(o[2*nt2],     pf[kt], &bV[0]);
                mma_bf16(o[2*nt2 + 1], pf[kt], &bV[2]);
            }
        }
        __syncthreads();
    }

    const float inv0 = (l0 > 0.f) ? 1.f / l0 : 0.f;
    const float inv1 = (l1 > 0.f) ? 1.f / l1 : 0.f;
    const size_t row0 = rowbase + q0 + wid * 16 + r0;
    #pragma unroll
    for (int nt = 0; nt < 8; nt++) {
        const int n = colh + nt * 8 + cq;
        *(uint32_t*)&OH[row0 * DD + n]       = pkbf(o[nt][0] * inv0, o[nt][1] * inv0);
        *(uint32_t*)&OH[(row0 + 8) * DD + n] = pkbf(o[nt][2] * inv1, o[nt][3] * inv1);
    }
}

// ---------------------------------------------------------------------------
// Row LayerNorm; F16OUT=1 additionally emits fp16 copy of the output.
// ---------------------------------------------------------------------------
template<int F16OUT>
__global__ __launch_bounds__(256)
void ln_kernel(const float* __restrict__ Y, const float* __restrict__ sc,
               const float* __restrict__ bi, float* __restrict__ X,
               __half* __restrict__ outF)
{
    const int row = blockIdx.x;
    const int tid = threadIdx.x;
    const float4 v = ((const float4*)(Y + (size_t)row * DD))[tid];

    float s  = v.x + v.y + v.z + v.w;
    float ss = v.x*v.x + v.y*v.y + v.z*v.z + v.w*v.w;
    #pragma unroll
    for (int off = 16; off >= 1; off >>= 1) {
        s  += __shfl_xor_sync(0xffffffffu, s,  off);
        ss += __shfl_xor_sync(0xffffffffu, ss, off);
    }

    __shared__ float ws[8], wss[8];
    __shared__ float mean_sh, rstd_sh;
    if ((tid & 31) == 0) { ws[tid >> 5] = s; wss[tid >> 5] = ss; }
    __syncthreads();
    if (tid == 0) {
        float S = 0.f, SS = 0.f;
        #pragma unroll
        for (int k = 0; k < 8; k++) { S += ws[k]; SS += wss[k]; }
        float mu = S / (float)DD;
        float var = SS / (float)DD - mu * mu;
        mean_sh = mu;
        rstd_sh = rsqrtf(var + 1e-5f);
    }
    __syncthreads();
    const float mu = mean_sh, rs = rstd_sh;

    const float4 sc4 = ((const float4*)sc)[tid];
    const float4 b4  = ((const float4*)bi)[tid];
    float4 o;
    o.x = (v.x - mu) * rs * sc4.x + b4.x;
    o.y = (v.y - mu) * rs * sc4.y + b4.y;
    o.z = (v.z - mu) * rs * sc4.z + b4.z;
    o.w = (v.w - mu) * rs * sc4.w + b4.w;
    ((float4*)(X + (size_t)row * DD))[tid] = o;

    if (F16OUT) {
        uint2 fv = make_uint2(pkhf(o.x, o.y), pkhf(o.z, o.w));
        *(uint2*)&outF[(size_t)row * DD + tid * 4] = fv;
    }
}

// ---------------------------------------------------------------------------
// Launch
// ---------------------------------------------------------------------------
extern "C" void kernel_launch(void* const* d_in, const int* in_sizes, int n_in,
                              void* d_out, int out_size)
{
    const float* src  = (const float*)d_in[0];
    const void*  mask_raw = d_in[1];
    const float* q_w = (const float*)d_in[2];
    const float* q_b = (const float*)d_in[3];
    const float* k_w = (const float*)d_in[4];
    const float* k_b = (const float*)d_in[5];
    const float* v_w = (const float*)d_in[6];
    const float* v_b = (const float*)d_in[7];
    const float* o_w = (const float*)d_in[8];
    const float* o_b = (const float*)d_in[9];
    const float* l1_w = (const float*)d_in[10];
    const float* l1_b = (const float*)d_in[11];
    const float* l2_w = (const float*)d_in[12];
    const float* l2_b = (const float*)d_in[13];
    const float* n1_s = (const float*)d_in[14];
    const float* n1_b = (const float*)d_in[15];
    const float* n2_s = (const float*)d_in[16];
    const float* n2_b = (const float*)d_in[17];
    const float* alpha_attn = (const float*)d_in[18];
    const float* alpha_ff   = (const float*)d_in[19];

    float *y, *x, *qkvb;
    unsigned char* maskc;
    __nv_bfloat16 *srcB, *qkvB, *attnB, *qkvw, *owH;
    __half *xF, *hF, *l1F, *l2F;
    cudaGetSymbolAddress((void**)&y,     g_y);
    cudaGetSymbolAddress((void**)&x,     g_x);
    cudaGetSymbolAddress((void**)&maskc, g_mask);
    cudaGetSymbolAddress((void**)&srcB,  g_srcB);
    cudaGetSymbolAddress((void**)&qkvB,  g_qkvB);
    cudaGetSymbolAddress((void**)&attnB, g_attnB);
    cudaGetSymbolAddress((void**)&xF,    g_xF);
    cudaGetSymbolAddress((void**)&hF,    g_hF);
    cudaGetSymbolAddress((void**)&qkvw,  g_qkvw);
    cudaGetSymbolAddress((void**)&qkvb,  g_qkvb);
    cudaGetSymbolAddress((void**)&owH,   g_owH);
    cudaGetSymbolAddress((void**)&l1F,   g_l1F);
    cudaGetSymbolAddress((void**)&l2F,   g_l2F);

    cudaFuncSetAttribute((const void*)gemm_bf<2,0>, cudaFuncAttributeMaxDynamicSharedMemorySize, GBF_DYN);
    cudaFuncSetAttribute((const void*)gemm_bf<3,0>, cudaFuncAttributeMaxDynamicSharedMemorySize, GBF_DYN);
    cudaFuncSetAttribute((const void*)gemm_bf<2,1>, cudaFuncAttributeMaxDynamicSharedMemorySize, GBF_DYN);
    cudaFuncSetAttribute((const void*)gemm_bf<5,1>, cudaFuncAttributeMaxDynamicSharedMemorySize, GBF_DYN);
    cudaFuncSetAttribute(flash_attn_tc, cudaFuncAttributeMaxDynamicSharedMemorySize, ATT_SMEM);

    dim3 blk(256);
    dim3 grid_qkv(QLD/128, MM/128);   // (24, 32) merged
    dim3 grid_d(DD/128, MM/128);      // (8, 32)
    dim3 grid_ff1(FF/128, MM/128);    // (32, 32)

    // Mask canonicalization
    mask_scan_kernel<<<1, 1024>>>((const uint32_t*)mask_raw);
    mask_convert_kernel<<<(TT*TT/4 + 255)/256, 256>>>(mask_raw);

    // All conversions in one launch + bias concat
    convert_all<<<16384, 256>>>(q_w, k_w, v_w, o_w, l1_w, l2_w, src);
    concat_bias<<<(QLD + 255)/256, 256>>>(q_b, k_b, v_b);

    // Merged QKV projection (1-term bf16) -> bf16 [M, 3D]
    gemm_bf<3,0><<<grid_qkv, blk, GBF_DYN>>>(srcB, qkvw, qkvb, nullptr, MM, QLD, DD, nullptr, nullptr, qkvB);

    // Flash attention -> plain bf16
    flash_attn_tc<<<dim3(TT/128, HH, BB), blk, ATT_SMEM>>>(qkvB, maskc, attnB);

    // O projection (1-term bf16) + residual, LN1 (emits fp16 x)
    gemm_bf<2,0><<<grid_d, blk, GBF_DYN>>>(attnB, owH, o_b, y, MM, DD, DD, src, alpha_attn, nullptr);
    ln_kernel<1><<<MM, 256>>>(y, n1_s, n1_b, x, xF);

    // FFN (1-term fp16)
    gemm_bf<5,1><<<grid_ff1, blk, GBF_DYN>>>(xF, l1F, l1_b, nullptr, MM, FF, DD, nullptr, nullptr, hF);
    gemm_bf<2,1><<<grid_d, blk, GBF_DYN>>>(hF, l2F, l2_b, y, MM, DD, FF, x, alpha_ff, nullptr);
    ln_kernel<0><<<MM, 256>>>(y, n2_s, n2_b, (float*)d_out, nullptr);
}

// round 17
// speedup vs baseline: 1.0299x; 1.0299x over previous
#include <cuda_runtime.h>
#include <cuda_bf16.h>
#include <cuda_fp16.h>
#include <math.h>
#include <stdint.h>

// Problem constants
#define BB 2
#define TT 2048
#define DD 1024
#define HH 16
#define DHH 64
#define FF 4096
#define MM (BB*TT)          // 4096 rows
#define QLD (3*DD)          // merged qkv row stride

// ---------------------------------------------------------------------------
// Baseline-PTX tensor helpers
// ---------------------------------------------------------------------------
__device__ __forceinline__ uint32_t smem_u32(const void* p) {
    uint32_t a;
    asm("{ .reg .u64 t; cvta.to.shared.u64 t, %1; cvt.u32.u64 %0, t; }" : "=r"(a) : "l"(p));
    return a;
}
__device__ __forceinline__ void cpa16(uint32_t dst, const void* src) {
    asm volatile("cp.async.cg.shared.global [%0], [%1], 16;" :: "r"(dst), "l"(src) : "memory");
}
#define CP_COMMIT() asm volatile("cp.async.commit_group;" ::: "memory")
#define CP_WAIT0()  asm volatile("cp.async.wait_group 0;" ::: "memory")
#define CP_WAIT1()  asm volatile("cp.async.wait_group 1;" ::: "memory")

#define LDM4(r, a) \
    asm volatile("ldmatrix.sync.aligned.m8n8.x4.shared.b16 {%0,%1,%2,%3}, [%4];" \
        : "=r"((r)[0]), "=r"((r)[1]), "=r"((r)[2]), "=r"((r)[3]) : "r"(a))
#define LDM4T(r, a) \
    asm volatile("ldmatrix.sync.aligned.m8n8.x4.trans.shared.b16 {%0,%1,%2,%3}, [%4];" \
        : "=r"((r)[0]), "=r"((r)[1]), "=r"((r)[2]), "=r"((r)[3]) : "r"(a))

__device__ __forceinline__ void mma_bf16(float* d, const uint32_t* a, const uint32_t* b) {
    asm volatile("mma.sync.aligned.m16n8k16.row.col.f32.bf16.bf16.f32 "
        "{%0,%1,%2,%3}, {%4,%5,%6,%7}, {%8,%9}, {%0,%1,%2,%3};"
        : "+f"(d[0]), "+f"(d[1]), "+f"(d[2]), "+f"(d[3])
        : "r"(a[0]), "r"(a[1]), "r"(a[2]), "r"(a[3]), "r"(b[0]), "r"(b[1]));
}
__device__ __forceinline__ void mma_fp16(float* d, const uint32_t* a, const uint32_t* b) {
    asm volatile("mma.sync.aligned.m16n8k16.row.col.f32.f16.f16.f32 "
        "{%0,%1,%2,%3}, {%4,%5,%6,%7}, {%8,%9}, {%0,%1,%2,%3};"
        : "+f"(d[0]), "+f"(d[1]), "+f"(d[2]), "+f"(d[3])
        : "r"(a[0]), "r"(a[1]), "r"(a[2]), "r"(a[3]), "r"(b[0]), "r"(b[1]));
}

__device__ __forceinline__ uint32_t pkbf(float lo, float hi) {
    uint32_t d;
    asm("cvt.rn.bf16x2.f32 %0, %1, %2;" : "=r"(d) : "f"(hi), "f"(lo));
    return d;
}
__device__ __forceinline__ uint32_t pkhf(float lo, float hi) {
    uint32_t d;
    asm("cvt.rn.f16x2.f32 %0, %1, %2;" : "=r"(d) : "f"(hi), "f"(lo));
    return d;
}
__device__ __forceinline__ float ex2(float x) {
    float r;
    asm("ex2.approx.f32 %0, %1;" : "=f"(r) : "f"(x));
    return r;
}

// ---------------------------------------------------------------------------
// Scratch (allocation-free: __device__ globals)
// ---------------------------------------------------------------------------
__device__ float g_y[MM*DD];
__device__ float g_x[MM*DD];
__device__ unsigned char g_mask[TT*TT];
__device__ int g_mask_mode;

__device__ __nv_bfloat16 g_srcB[MM*DD];
__device__ __nv_bfloat16 g_qkvB[MM*QLD];
__device__ __nv_bfloat16 g_attnB[MM*DD];
__device__ __half        g_xF[MM*DD];
__device__ __half        g_hF[MM*FF];
__device__ __nv_bfloat16 g_qkvw[QLD*DD];
__device__ float         g_qkvb[QLD];
__device__ __nv_bfloat16 g_owH[DD*DD];
__device__ __half        g_l1F[FF*DD];
__device__ __half        g_l2F[DD*FF];

// ---------------------------------------------------------------------------
// One fused conversion kernel: weights + src + qkv bias concat.
// float4 index layout: [0,3WQ) qkvw | [3WQ,4WQ) ow | +L1 l1 | +L1 l2 | +L1 src
// Tail blocks (>= 16384) handle the bias concat.
// ---------------------------------------------------------------------------
#define CVT_MAIN_BLOCKS 16384
__global__ __launch_bounds__(256)
void convert_all(const float* __restrict__ qw, const float* __restrict__ kw,
                 const float* __restrict__ vw, const float* __restrict__ ow,
                 const float* __restrict__ l1w, const float* __restrict__ l2w,
                 const float* __restrict__ src,
                 const float* __restrict__ qb, const float* __restrict__ kb,
                 const float* __restrict__ vb)
{
    const int WQ = DD*DD/4;
    const int L1 = FF*DD/4;
    if (blockIdx.x >= CVT_MAIN_BLOCKS) {
        int i = (blockIdx.x - CVT_MAIN_BLOCKS) * 256 + threadIdx.x;
        if (i < QLD)
            g_qkvb[i] = (i < DD) ? qb[i] : (i < 2*DD) ? kb[i - DD] : vb[i - 2*DD];
        return;
    }
    int i = blockIdx.x * 256 + threadIdx.x;
    if (i < 4*WQ) {
        int t = i / WQ;
        int j = i - t*WQ;
        const float* w = (t == 0) ? qw : (t == 1) ? kw : (t == 2) ? vw : ow;
        float4 v = ((const float4*)w)[j];
        uint2 o = make_uint2(pkbf(v.x, v.y), pkbf(v.z, v.w));
        if (t < 3) ((uint2*)g_qkvw)[i] = o;
        else       ((uint2*)g_owH)[j] = o;
    } else {
        int r = i - 4*WQ;
        int t = r / L1;
        int j = r - t*L1;
        const float* w = (t == 0) ? l1w : (t == 1) ? l2w : src;
        float4 v = ((const float4*)w)[j];
        if (t == 0)      ((uint2*)g_l1F)[j] = make_uint2(pkhf(v.x, v.y), pkhf(v.z, v.w));
        else if (t == 1) ((uint2*)g_l2F)[j] = make_uint2(pkhf(v.x, v.y), pkhf(v.z, v.w));
        else             ((uint2*)g_srcB)[j] = make_uint2(pkbf(v.x, v.y), pkbf(v.z, v.w));
    }
}

// ---------------------------------------------------------------------------
// Mask dtype detection (prefix scan) + convert
// ---------------------------------------------------------------------------
__global__ __launch_bounds__(1024)
void mask_scan_kernel(const uint32_t* __restrict__ m)
{
    const int tid = threadIdx.x;
    int u8f = 0, f32f = 0;
    const int NW = 65536;
    for (int i = tid; i < NW; i += 1024) {
        uint32_t w = m[i];
        if (w != 0u && w != 1u && w != 0x3F800000u) u8f = 1;
        if (w == 0x3F800000u) f32f = 1;
    }
    __shared__ int s_u8, s_f32;
    if (tid == 0) { s_u8 = 0; s_f32 = 0; }
    __syncthreads();
    if (u8f)  atomicOr(&s_u8, 1);
    if (f32f) atomicOr(&s_f32, 1);
    __syncthreads();
    if (tid == 0)
        g_mask_mode = s_u8 ? 0 : (s_f32 ? 2 : 1);
}

__global__ __launch_bounds__(256)
void mask_convert_kernel(const void* __restrict__ min)
{
    const int mode = g_mask_mode;
    int i = blockIdx.x * blockDim.x + threadIdx.x;
    const int NW = (TT*TT) / 4;
    if (i >= NW) return;
    uint32_t out;
    if (mode == 0) {
        out = ((const uint32_t*)min)[i];
    } else if (mode == 1) {
        const int* p = (const int*)min;
        out  = (uint32_t)(p[4*i+0] != 0);
        out |= (uint32_t)(p[4*i+1] != 0) << 8;
        out |= (uint32_t)(p[4*i+2] != 0) << 16;
        out |= (uint32_t)(p[4*i+3] != 0) << 24;
    } else {
        const float* p = (const float*)min;
        out  = (uint32_t)(p[4*i+0] != 0.f);
        out |= (uint32_t)(p[4*i+1] != 0.f) << 8;
        out |= (uint32_t)(p[4*i+2] != 0.f) << 16;
        out |= (uint32_t)(p[4*i+3] != 0.f) << 24;
    }
    ((uint32_t*)g_mask)[i] = out;
}

// ---------------------------------------------------------------------------
// Persistent 1-term GEMM via mma.sync, 3-stage cp.async pipeline.
// Grid is 1-D persistent: CTAs stripe over (M/128)x(N/128) tiles.
// EPI: 2 = res + alpha*(acc+bias) -> f32 C
//      3 = bias -> 16-bit out
//      5 = bias+relu -> 16-bit out
// HALF: 0 = bf16, 1 = fp16
// ---------------------------------------------------------------------------
#define TILE_B   16384
#define BSTAGE_B (2*TILE_B)
#define GBF_DYN  (3*BSTAGE_B + 1024)

#define STAGE_CHUNK(st, k0) do { \
    _Pragma("unroll") \
    for (int j = 0; j < 4; j++) { \
        const int c = sc0 + j; \
        const uint32_t sw = swrowbase + ((uint32_t)(c ^ rx) << 4); \
        cpa16((st) + sw,          A + (size_t)(bm + srow) * K + (k0) + c * 8); \
        cpa16((st) + TILE_B + sw, B + (size_t)(bn + srow) * K + (k0) + c * 8); \
    } } while (0)

template<int EPI, int HALF>
__global__ __launch_bounds__(256, 2)
void gemm_bf(const void* __restrict__ Av, const void* __restrict__ Bv,
             const float* __restrict__ bias, float* __restrict__ C,
             int M, int N, int K,
             const float* __restrict__ res, const float* __restrict__ alpha_p,
             void* __restrict__ outv)
{
    const uint16_t* A = (const uint16_t*)Av;
    const uint16_t* B = (const uint16_t*)Bv;
    uint16_t* out = (uint16_t*)outv;

    extern __shared__ unsigned char sm[];
    const uint32_t smu  = smem_u32(sm);
    const uint32_t base = (smu + 1023) & ~1023u;

    const int tid  = threadIdx.x;
    const int wid  = tid >> 5;
    const int lane = tid & 31;
    const int wm   = wid >> 2;
    const int wn   = wid & 3;

    const int srow = tid >> 1;
    const int sc0  = (tid & 1) * 4;
    const uint32_t swrowbase = (uint32_t)srow * 128;
    const int rx = srow & 7;

    const int NC  = K >> 6;
    const int NTX = N >> 7;
    const int NT  = (M >> 7) * NTX;

    float alpha = 0.f;
    if (EPI == 2) alpha = *alpha_p;

    for (int t = blockIdx.x; t < NT; t += gridDim.x) {
        const int bm = (t / NTX) * 128;
        const int bn = (t % NTX) * 128;

        float d[4][4][4];
        #pragma unroll
        for (int i = 0; i < 4; i++)
            #pragma unroll
            for (int j = 0; j < 4; j++)
                #pragma unroll
                for (int q = 0; q < 4; q++) d[i][j][q] = 0.f;

        __syncthreads();   // prior tile's smem readers done before restage

        STAGE_CHUNK(base, 0);
        CP_COMMIT();
        if (NC > 1) STAGE_CHUNK(base + BSTAGE_B, 64);
        CP_COMMIT();

        for (int ch = 0; ch < NC; ch++) {
            CP_WAIT1();
            __syncthreads();

            if (ch + 2 < NC) {
                const uint32_t st = base + ((ch + 2) % 3) * BSTAGE_B;
                STAGE_CHUNK(st, (size_t)(ch + 2) * 64);
            }
            CP_COMMIT();

            const uint32_t st = base + (ch % 3) * BSTAGE_B;
            const uint32_t aS = st, bS = st + TILE_B;

            const int arow_base = wm * 64 + (lane & 15);
            const int akh = lane >> 4;
            const int brow_base = wn * 32 + (lane & 7) + ((lane >> 4) << 3);
            const int bkh = (lane >> 3) & 1;

            #pragma unroll
            for (int k16 = 0; k16 < 4; k16++) {
                uint32_t a[4][4], b[2][4];
                #pragma unroll
                for (int mt = 0; mt < 4; mt++) {
                    const int row = arow_base + mt * 16;
                    const uint32_t cb = (uint32_t)(k16 * 32 + akh * 16);
                    LDM4(a[mt], aS + (uint32_t)row * 128 + (cb ^ ((uint32_t)(row & 7) << 4)));
                }
                #pragma unroll
                for (int bt = 0; bt < 2; bt++) {
                    const int row = brow_base + bt * 16;
                    const uint32_t cb = (uint32_t)(k16 * 32 + bkh * 16);
                    LDM4(b[bt], bS + (uint32_t)row * 128 + (cb ^ ((uint32_t)(row & 7) << 4)));
                }
                #pragma unroll
                for (int mt = 0; mt < 4; mt++)
                    #pragma unroll
                    for (int nt = 0; nt < 4; nt++) {
                        if (HALF) mma_fp16(d[mt][nt], a[mt], &b[nt >> 1][(nt & 1) * 2]);
                        else      mma_bf16(d[mt][nt], a[mt], &b[nt >> 1][(nt & 1) * 2]);
                    }
            }
        }

        const int g  = lane >> 2;
        const int nq = (lane & 3) * 2;

        #pragma unroll
        for (int mt = 0; mt < 4; mt++) {
            const int m0 = bm + wm * 64 + mt * 16 + g;
            #pragma unroll
            for (int nt = 0; nt < 4; nt++) {
                const int n = bn + wn * 32 + nt * 8 + nq;
                float2 b2 = *(const float2*)&bias[n];
                float2 o0 = make_float2(d[mt][nt][0] + b2.x, d[mt][nt][1] + b2.y);
                float2 o1 = make_float2(d[mt][nt][2] + b2.x, d[mt][nt][3] + b2.y);
                if (EPI == 5) {
                    o0.x = fmaxf(o0.x, 0.f); o0.y = fmaxf(o0.y, 0.f);
                    o1.x = fmaxf(o1.x, 0.f); o1.y = fmaxf(o1.y, 0.f);
                }
                if (EPI == 2) {
                    float2 r0 = *(const float2*)&res[(size_t)m0 * N + n];
                    float2 r1 = *(const float2*)&res[(size_t)(m0 + 8) * N + n];
                    o0.x = r0.x + alpha * o0.x; o0.y = r0.y + alpha * o0.y;
                    o1.x = r1.x + alpha * o1.x; o1.y = r1.y + alpha * o1.y;
                    *(float2*)&C[(size_t)m0 * N + n]       = o0;
                    *(float2*)&C[(size_t)(m0 + 8) * N + n] = o1;
                } else {
                    uint32_t p0 = HALF ? pkhf(o0.x, o0.y) : pkbf(o0.x, o0.y);
                    uint32_t p1 = HALF ? pkhf(o1.x, o1.y) : pkbf(o1.x, o1.y);
                    *(uint32_t*)&out[(size_t)m0 * N + n]       = p0;
                    *(uint32_t*)&out[(size_t)(m0 + 8) * N + n] = p1;
                }
            }
        }
    }
}

// ---------------------------------------------------------------------------
// Tensor-core flash attention (bf16 mma, fp32 softmax, exp2 domain).
// Masked sentinel = -30000 (log2 domain); running max clamped >= 0 so masked
// probabilities underflow to exactly 0 in ex2.approx — no per-element select.
// ---------------------------------------------------------------------------
#define MPAD 80
#define KV_B  8192
#define MB_B  (128*MPAD)
#define BUF_B (2*KV_B + MB_B)
#define ATT_SMEM (16384 + 2*BUF_B + 1024)
#define SCL2 0.1803368801f   // 0.125 * log2(e)
#define MSENT (-30000.f)

__global__ __launch_bounds__(256, 2)
void flash_attn_tc(const __nv_bfloat16* __restrict__ QKV,
                   const unsigned char* __restrict__ mask,
                   __nv_bfloat16* __restrict__ OH)
{
    extern __shared__ unsigned char sm[];
    const uint32_t smu = smem_u32(sm);
    const uint32_t Qs  = (smu + 1023) & ~1023u;

    const int tid = threadIdx.x, wid = tid >> 5, lane = tid & 31;
    const int q0 = blockIdx.x * 128;
    const int h  = blockIdx.y, b = blockIdx.z;
    const size_t rowbase = (size_t)b * TT;
    const int colh = h * DHH;

    {
        const int r = tid >> 1, c0 = (tid & 1) * 4;
        const __nv_bfloat16* src = QKV + (rowbase + q0 + r) * QLD + colh;
        #pragma unroll
        for (int j = 0; j < 4; j++) {
            const int c = c0 + j;
            cpa16(Qs + r * 128 + ((uint32_t)(c ^ (r & 7)) << 4), src + c * 8);
        }
    }
    {
        const uint32_t Ks = Qs + 16384, Vs = Ks + KV_B, Ms = Vs + KV_B;
        const int r = tid >> 2;
        const int j2 = tid & 3;
        #pragma unroll
        for (int j = 0; j < 2; j++) {
            const int c = j2 * 2 + j;
            const uint32_t sw = r * 128 + ((uint32_t)(c ^ (r & 7)) << 4);
            cpa16(Ks + sw, QKV + (rowbase + r) * QLD + DD + colh + c * 8);
            cpa16(Vs + sw, QKV + (rowbase + r) * QLD + 2*DD + colh + c * 8);
        }
        const int mr = tid >> 1;
        #pragma unroll
        for (int j = 0; j < 2; j++) {
            const int c = (tid & 1) * 2 + j;
            cpa16(Ms + mr * MPAD + c * 16, mask + (size_t)(q0 + mr) * TT + c * 16);
        }
        CP_COMMIT();
    }

    float m0 = 0.f, m1 = 0.f, l0 = 0.f, l1 = 0.f;
    float o[8][4];
    #pragma unroll
    for (int i = 0; i < 8; i++)
        #pragma unroll
        for (int j = 0; j < 4; j++) o[i][j] = 0.f;

    uint32_t aQ[4][4];
    const int arow = wid * 16 + (lane & 15);
    const int akh  = lane >> 4;
    const int brow = (lane & 7) + ((lane >> 4) << 3);
    const int bkh  = (lane >> 3) & 1;
    const int r0   = lane >> 2;
    const int cq   = (lane & 3) * 2;

    const int NT = TT / 64;
    for (int st = 0; st < NT; st++) {
        if (st + 1 < NT) {
            const uint32_t base = Qs + 16384 + ((st + 1) & 1) * BUF_B;
            const uint32_t Ks = base, Vs = base + KV_B, Ms = base + 2*KV_B;
            const int s1 = (st + 1) * 64;
            const int r = tid >> 2, j2 = tid & 3;
            #pragma unroll
            for (int j = 0; j < 2; j++) {
                const int c = j2 * 2 + j;
                const uint32_t sw = r * 128 + ((uint32_t)(c ^ (r & 7)) << 4);
                cpa16(Ks + sw, QKV + (rowbase + s1 + r) * QLD + DD + colh + c * 8);
                cpa16(Vs + sw, QKV + (rowbase + s1 + r) * QLD + 2*DD + colh + c * 8);
            }
            const int mr = tid >> 1;
            #pragma unroll
            for (int j = 0; j < 2; j++) {
                const int c = (tid & 1) * 2 + j;
                cpa16(Ms + mr * MPAD + c * 16, mask + (size_t)(q0 + mr) * TT + s1 + c * 16);
            }
            CP_COMMIT();
            CP_WAIT1();
        } else {
            CP_WAIT0();
        }
        __syncthreads();

        if (st == 0) {
            #pragma unroll
            for (int kt = 0; kt < 4; kt++) {
                const uint32_t cb = (uint32_t)(kt * 32 + akh * 16);
                LDM4(aQ[kt], Qs + (uint32_t)arow * 128 + (cb ^ ((uint32_t)(arow & 7) << 4)));
            }
        }

        const uint32_t base = Qs + 16384 + (st & 1) * BUF_B;
        const uint32_t Ks = base, Vs = base + KV_B, Ms = base + 2*KV_B;

        float sacc[8][4];
        #pragma unroll
        for (int i = 0; i < 8; i++)
            #pragma unroll
            for (int j = 0; j < 4; j++) sacc[i][j] = 0.f;

        #pragma unroll
        for (int kt = 0; kt < 4; kt++) {
            uint32_t bK[4][4];
            #pragma unroll
            for (int bt = 0; bt < 4; bt++) {
                const int row = brow + bt * 16;
                const uint32_t cb = (uint32_t)(kt * 32 + bkh * 16);
                LDM4(bK[bt], Ks + (uint32_t)row * 128 + (cb ^ ((uint32_t)(row & 7) << 4)));
            }
            #pragma unroll
            for (int nt = 0; nt < 8; nt++)
                mma_bf16(sacc[nt], aQ[kt], &bK[nt >> 1][(nt & 1) * 2]);
        }

        // masked online softmax (log2 domain, sentinel underflow)
        const int mrow0 = wid * 16 + r0;
        float mx0 = MSENT, mx1 = MSENT;
        #pragma unroll
        for (int nt = 0; nt < 8; nt++) {
            uchar2 k0 = *(const uchar2*)(sm + (Ms - smu) + mrow0 * MPAD + nt * 8 + cq);
            uchar2 k1 = *(const uchar2*)(sm + (Ms - smu) + (mrow0 + 8) * MPAD + nt * 8 + cq);
            sacc[nt][0] = k0.x ? MSENT : sacc[nt][0] * SCL2;
            sacc[nt][1] = k0.y ? MSENT : sacc[nt][1] * SCL2;
            sacc[nt][2] = k1.x ? MSENT : sacc[nt][2] * SCL2;
            sacc[nt][3] = k1.y ? MSENT : sacc[nt][3] * SCL2;
            mx0 = fmaxf(mx0, fmaxf(sacc[nt][0], sacc[nt][1]));
            mx1 = fmaxf(mx1, fmaxf(sacc[nt][2], sacc[nt][3]));
        }
        mx0 = fmaxf(mx0, __shfl_xor_sync(0xffffffffu, mx0, 1));
        mx0 = fmaxf(mx0, __shfl_xor_sync(0xffffffffu, mx0, 2));
        mx1 = fmaxf(mx1, __shfl_xor_sync(0xffffffffu, mx1, 1));
        mx1 = fmaxf(mx1, __shfl_xor_sync(0xffffffffu, mx1, 2));

        // running max clamped >= 0 (m init 0): masked rows keep mn = m >= 0, so
        // ex2(MSENT - mn) == 0 exactly; normalization unaffected (shared offset).
        const float mn0 = fmaxf(m0, mx0), mn1 = fmaxf(m1, mx1);
        const float af0 = ex2(m0 - mn0), af1 = ex2(m1 - mn1);
        float rs0 = 0.f, rs1 = 0.f;
        #pragma unroll
        for (int nt = 0; nt < 8; nt++) {
            float p0 = ex2(sacc[nt][0] - mn0);
            float p1 = ex2(sacc[nt][1] - mn0);
            float p2 = ex2(sacc[nt][2] - mn1);
            float p3 = ex2(sacc[nt][3] - mn1);
            sacc[nt][0] = p0; sacc[nt][1] = p1; sacc[nt][2] = p2; sacc[nt][3] = p3;
            rs0 += p0 + p1; rs1 += p2 + p3;
        }
        rs0 += __shfl_xor_sync(0xffffffffu, rs0, 1);
        rs0 += __shfl_xor_sync(0xffffffffu, rs0, 2);
        rs1 += __shfl_xor_sync(0xffffffffu, rs1, 1);
        rs1 += __shfl_xor_sync(0xffffffffu, rs1, 2);
        l0 = af0 * l0 + rs0;  m0 = mn0;
        l1 = af1 * l1 + rs1;  m1 = mn1;

        #pragma unroll
        for (int nt = 0; nt < 8; nt++) {
            o[nt][0] *= af0; o[nt][1] *= af0;
            o[nt][2] *= af1; o[nt][3] *= af1;
        }

        uint32_t pf[4][4];
        #pragma unroll
        for (int kt = 0; kt < 4; kt++) {
            pf[kt][0] = pkbf(sacc[2*kt][0],   sacc[2*kt][1]);
            pf[kt][1] = pkbf(sacc[2*kt][2],   sacc[2*kt][3]);
            pf[kt][2] = pkbf(sacc[2*kt+1][0], sacc[2*kt+1][1]);
            pf[kt][3] = pkbf(sacc[2*kt+1][2], sacc[2*kt+1][3]);
        }

        #pragma unroll
        for (int kt = 0; kt < 4; kt++) {
            #pragma unroll
            for (int nt2 = 0; nt2 < 4; nt2++) {
                uint32_t bV[4];
                const int rv = kt * 16 + (lane & 15);
                const uint32_t c = (uint32_t)(nt2 * 2 + (lane >> 4));
                LDM4T(bV, Vs + (uint32_t)rv * 128 + ((c ^ (uint32_t)(rv & 7)) << 4));
                mma_bf16(o[2*nt2],     pf[kt], &bV[0]);
                mma_bf16(o[2*nt2 + 1], pf[kt], &bV[2]);
            }
        }
        __syncthreads();
    }

    const float inv0 = (l0 > 0.f) ? 1.f / l0 : 0.f;
    const float inv1 = (l1 > 0.f) ? 1.f / l1 : 0.f;
    const size_t row0 = rowbase + q0 + wid * 16 + r0;
    #pragma unroll
    for (int nt = 0; nt < 8; nt++) {
        const int n = colh + nt * 8 + cq;
        *(uint32_t*)&OH[row0 * DD + n]       = pkbf(o[nt][0] * inv0, o[nt][1] * inv0);
        *(uint32_t*)&OH[(row0 + 8) * DD + n] = pkbf(o[nt][2] * inv1, o[nt][3] * inv1);
    }
}

// ---------------------------------------------------------------------------
// Row LayerNorm; F16OUT=1 additionally emits fp16 copy of the output.
// ---------------------------------------------------------------------------
template<int F16OUT>
__global__ __launch_bounds__(256)
void ln_kernel(const float* __restrict__ Y, const float* __restrict__ sc,
               const float* __restrict__ bi, float* __restrict__ X,
               __half* __restrict__ outF)
{
    const int row = blockIdx.x;
    const int tid = threadIdx.x;
    const float4 v = ((const float4*)(Y + (size_t)row * DD))[tid];

    float s  = v.x + v.y + v.z + v.w;
    float ss = v.x*v.x + v.y*v.y + v.z*v.z + v.w*v.w;
    #pragma unroll
    for (int off = 16; off >= 1; off >>= 1) {
        s  += __shfl_xor_sync(0xffffffffu, s,  off);
        ss += __shfl_xor_sync(0xffffffffu, ss, off);
    }

    __shared__ float ws[8], wss[8];
    __shared__ float mean_sh, rstd_sh;
    if ((tid & 31) == 0) { ws[tid >> 5] = s; wss[tid >> 5] = ss; }
    __syncthreads();
    if (tid == 0) {
        float S = 0.f, SS = 0.f;
        #pragma unroll
        for (int k = 0; k < 8; k++) { S += ws[k]; SS += wss[k]; }
        float mu = S / (float)DD;
        float var = SS / (float)DD - mu * mu;
        mean_sh = mu;
        rstd_sh = rsqrtf(var + 1e-5f);
    }
    __syncthreads();
    const float mu = mean_sh, rs = rstd_sh;

    const float4 sc4 = ((const float4*)sc)[tid];
    const float4 b4  = ((const float4*)bi)[tid];
    float4 o;
    o.x = (v.x - mu) * rs * sc4.x + b4.x;
    o.y = (v.y - mu) * rs * sc4.y + b4.y;
    o.z = (v.z - mu) * rs * sc4.z + b4.z;
    o.w = (v.w - mu) * rs * sc4.w + b4.w;
    ((float4*)(X + (size_t)row * DD))[tid] = o;

    if (F16OUT) {
        uint2 fv = make_uint2(pkhf(o.x, o.y), pkhf(o.z, o.w));
        *(uint2*)&outF[(size_t)row * DD + tid * 4] = fv;
    }
}

// ---------------------------------------------------------------------------
// Launch
// ---------------------------------------------------------------------------
extern "C" void kernel_launch(void* const* d_in, const int* in_sizes, int n_in,
                              void* d_out, int out_size)
{
    const float* src  = (const float*)d_in[0];
    const void*  mask_raw = d_in[1];
    const float* q_w = (const float*)d_in[2];
    const float* q_b = (const float*)d_in[3];
    const float* k_w = (const float*)d_in[4];
    const float* k_b = (const float*)d_in[5];
    const float* v_w = (const float*)d_in[6];
    const float* v_b = (const float*)d_in[7];
    const float* o_w = (const float*)d_in[8];
    const float* o_b = (const float*)d_in[9];
    const float* l1_w = (const float*)d_in[10];
    const float* l1_b = (const float*)d_in[11];
    const float* l2_w = (const float*)d_in[12];
    const float* l2_b = (const float*)d_in[13];
    const float* n1_s = (const float*)d_in[14];
    const float* n1_b = (const float*)d_in[15];
    const float* n2_s = (const float*)d_in[16];
    const float* n2_b = (const float*)d_in[17];
    const float* alpha_attn = (const float*)d_in[18];
    const float* alpha_ff   = (const float*)d_in[19];

    float *y, *x, *qkvb;
    unsigned char* maskc;
    __nv_bfloat16 *srcB, *qkvB, *attnB, *qkvw, *owH;
    __half *xF, *hF, *l1F, *l2F;
    cudaGetSymbolAddress((void**)&y,     g_y);
    cudaGetSymbolAddress((void**)&x,     g_x);
    cudaGetSymbolAddress((void**)&maskc, g_mask);
    cudaGetSymbolAddress((void**)&srcB,  g_srcB);
    cudaGetSymbolAddress((void**)&qkvB,  g_qkvB);
    cudaGetSymbolAddress((void**)&attnB, g_attnB);
    cudaGetSymbolAddress((void**)&xF,    g_xF);
    cudaGetSymbolAddress((void**)&hF,    g_hF);
    cudaGetSymbolAddress((void**)&qkvw,  g_qkvw);
    cudaGetSymbolAddress((void**)&qkvb,  g_qkvb);
    cudaGetSymbolAddress((void**)&owH,   g_owH);
    cudaGetSymbolAddress((void**)&l1F,   g_l1F);
    cudaGetSymbolAddress((void**)&l2F,   g_l2F);

    cudaFuncSetAttribute((const void*)gemm_bf<2,0>, cudaFuncAttributeMaxDynamicSharedMemorySize, GBF_DYN);
    cudaFuncSetAttribute((const void*)gemm_bf<3,0>, cudaFuncAttributeMaxDynamicSharedMemorySize, GBF_DYN);
    cudaFuncSetAttribute((const void*)gemm_bf<2,1>, cudaFuncAttributeMaxDynamicSharedMemorySize, GBF_DYN);
    cudaFuncSetAttribute((const void*)gemm_bf<5,1>, cudaFuncAttributeMaxDynamicSharedMemorySize, GBF_DYN);
    cudaFuncSetAttribute(flash_attn_tc, cudaFuncAttributeMaxDynamicSharedMemorySize, ATT_SMEM);

    int sms = 0;
    cudaDeviceGetAttribute(&sms, cudaDevAttrMultiProcessorCount, 0);
    if (sms <= 0) sms = 148;
    const int pgrid = 2 * sms;       // persistent GEMM grid (2 CTAs/SM)

    dim3 blk(256);

    // Mask canonicalization
    mask_scan_kernel<<<1, 1024>>>((const uint32_t*)mask_raw);
    mask_convert_kernel<<<(TT*TT/4 + 255)/256, 256>>>(mask_raw);

    // All conversions (+ bias concat tail blocks) in one launch
    convert_all<<<CVT_MAIN_BLOCKS + 12, 256>>>(q_w, k_w, v_w, o_w, l1_w, l2_w, src,
                                               q_b, k_b, v_b);

    // Merged QKV projection (1-term bf16, persistent) -> bf16 [M, 3D]
    gemm_bf<3,0><<<pgrid, blk, GBF_DYN>>>(srcB, qkvw, qkvb, nullptr, MM, QLD, DD, nullptr, nullptr, qkvB);

    // Flash attention -> plain bf16
    flash_attn_tc<<<dim3(TT/128, HH, BB), blk, ATT_SMEM>>>(qkvB, maskc, attnB);

    // O projection (1-term bf16, persistent) + residual, LN1 (emits fp16 x)
    gemm_bf<2,0><<<pgrid, blk, GBF_DYN>>>(attnB, owH, o_b, y, MM, DD, DD, src, alpha_attn, nullptr);
    ln_kernel<1><<<MM, 256>>>(y, n1_s, n1_b, x, xF);

    // FFN (1-term fp16, persistent)
    gemm_bf<5,1><<<pgrid, blk, GBF_DYN>>>(xF, l1F, l1_b, nullptr, MM, FF, DD, nullptr, nullptr, hF);
    gemm_bf<2,1><<<pgrid, blk, GBF_DYN>>>(hF, l2F, l2_b, y, MM, DD, FF, x, alpha_ff, nullptr);
    ln_kernel<0><<<MM, 256>>>(y, n2_s, n2_b, (float*)d_out, nullptr);
}